// round 1
// baseline (speedup 1.0000x reference)
#include <cuda_runtime.h>
#include <math.h>

#define H 64
#define MAX_N 65536

// Scratch (static __device__ — no allocation in kernel_launch)
__device__ float g_f[MAX_N * H];      // feature * src_norm
__device__ float g_prop[MAX_N * H];   // scatter-add accumulator
__device__ int   g_degout[MAX_N];
__device__ int   g_degin[MAX_N];
__device__ float g_dstnorm[MAX_N];

__global__ void k_zero(int n) {
    int stride = gridDim.x * blockDim.x;
    int total = n * H;
    for (int i = blockIdx.x * blockDim.x + threadIdx.x; i < total; i += stride)
        g_prop[i] = 0.f;
    for (int i = blockIdx.x * blockDim.x + threadIdx.x; i < n; i += stride) {
        g_degout[i] = 0;
        g_degin[i] = 0;
    }
}

__global__ void k_deg(const int* __restrict__ src, const int* __restrict__ dst, int e) {
    int i = blockIdx.x * blockDim.x + threadIdx.x;
    if (i < e) {
        atomicAdd(&g_degout[src[i]], 1);
        atomicAdd(&g_degin[dst[i]], 1);
    }
}

__global__ void k_scale(const float* __restrict__ feat, int n) {
    int i = blockIdx.x * blockDim.x + threadIdx.x;
    int total = n * H;
    if (i < total) {
        int node = i >> 6;
        float dout = (float)g_degout[node];
        float sn = rsqrtf(fmaxf(dout, 1.f));
        g_f[i] = feat[i] * sn;
        if ((i & 63) == 0) {
            float din = (float)g_degin[node];
            g_dstnorm[node] = rsqrtf(fmaxf(din, 1.f));
        }
    }
}

// SpMM scatter: 16 threads per edge, one float4 per thread, vectorized red.
__global__ void k_spmm(const int* __restrict__ src, const int* __restrict__ dst, int e) {
    int t = blockIdx.x * blockDim.x + threadIdx.x;
    int edge = t >> 4;
    int lane = t & 15;
    if (edge < e) {
        int s = src[edge];
        int d = dst[edge];
        const float4* F = (const float4*)g_f;
        float4 v = F[(size_t)s * 16 + lane];
        float* p = g_prop + (size_t)d * H + lane * 4;
        asm volatile("red.global.add.v4.f32 [%0], {%1,%2,%3,%4};"
                     :: "l"(p), "f"(v.x), "f"(v.y), "f"(v.z), "f"(v.w)
                     : "memory");
    }
}

// Epilogue: one warp per node. prop *= dst_norm; h = sigmoid(prop.w + b);
// exact emulation of the 10-step halting recurrence (scalar), then closed-form x.
__global__ void k_epi(const float* __restrict__ feat,
                      const float* __restrict__ hw,
                      const float* __restrict__ hb,
                      const int* __restrict__ niter_p,
                      float* __restrict__ out, int n) {
    int warp = (blockIdx.x * blockDim.x + threadIdx.x) >> 5;
    int lane = threadIdx.x & 31;
    if (warp >= n) return;
    int node = warp;

    float dn = g_dstnorm[node];
    float p0 = g_prop[node * H + lane] * dn;
    float p1 = g_prop[node * H + lane + 32] * dn;

    // dot(prop, halt_w)
    float dot = hw[lane] * p0 + hw[lane + 32] * p1;
    #pragma unroll
    for (int o = 16; o > 0; o >>= 1)
        dot += __shfl_xor_sync(0xffffffffu, dot, o);
    float z = dot + hb[0];
    float h = 1.f / (1.f + expf(-z));

    int niter = niter_p ? *niter_p : 10;
    float niter_f = (float)niter;

    // Exact emulation of the halting recurrence (prop/h loop-invariant, so
    // x update simplifies: only iteration 0's p blends in `feature`;
    // every later active iteration contributes exactly `prop`).
    float steps = 1.f, sum_h = 0.f;
    bool cont = true;
    float pfirst = 1.f;
    int U = 0;  // iterations with cont true at start (x-update count)
    for (int t = 0; t < niter; ++t) {
        bool prob = (sum_h + h < 0.99f) && cont;
        if (cont) U++;
        float probf = prob ? 1.f : 0.f;
        steps += probf;
        sum_h += probf * h;
        bool condition = prob && (steps < niter_f);
        float p = condition ? sum_h : 1.f - sum_h;
        if (t == 0) pfirst = p;
        cont = cont && prob;
    }

    float cprop = pfirst + (float)(U - 1);
    float cfeat = 1.f - pfirst;

    float f0 = feat[node * H + lane];
    float f1 = feat[node * H + lane + 32];
    out[node * H + lane]      = (p0 * cprop + f0 * cfeat) / steps;
    out[node * H + lane + 32] = (p1 * cprop + f1 * cfeat) / steps;
    if (lane == 0) {
        out[(size_t)n * H + node] = steps;            // steps
        out[(size_t)n * H + n + node] = 1.f - sum_h;  // remainder
    }
}

extern "C" void kernel_launch(void* const* d_in, const int* in_sizes, int n_in,
                              void* d_out, int out_size) {
    const float* feat = (const float*)d_in[0];
    const int*   src  = (const int*)d_in[1];
    const int*   dst  = (const int*)d_in[2];
    const float* hw   = (const float*)d_in[3];
    const float* hb   = (const float*)d_in[4];
    const int*   nit  = (n_in >= 6) ? (const int*)d_in[5] : nullptr;

    int n = in_sizes[0] / H;
    int e = in_sizes[1];
    float* out = (float*)d_out;

    k_zero<<<512, 256>>>(n);
    k_deg<<<(e + 255) / 256, 256>>>(src, dst, e);
    k_scale<<<(n * H + 255) / 256, 256>>>(feat, n);
    {
        long long threads = (long long)e * 16;
        int blocks = (int)((threads + 255) / 256);
        k_spmm<<<blocks, 256>>>(src, dst, e);
    }
    k_epi<<<(n * 32 + 255) / 256, 256>>>(feat, hw, hb, nit, out, n);
}

// round 2
// speedup vs baseline: 1.4961x; 1.4961x over previous
#include <cuda_runtime.h>
#include <math.h>

#define H 64
#define MAX_N 65536
#define CAP 64
#define MAX_OVF 65536

// Static scratch (no allocation in kernel_launch)
__device__ int   g_ebuf[MAX_N * CAP];   // dst-binned src indices
__device__ int   g_cnt[MAX_N];          // in-degree / bin cursor
__device__ int   g_degout[MAX_N];       // out-degree
__device__ float g_srcnorm[MAX_N];      // rsqrt(max(degout,1))
__device__ int2  g_ovf[MAX_OVF];        // overflow (dst, src) pairs
__device__ int   g_ovf_n;

__global__ void k_zero(int n) {
    int i = blockIdx.x * blockDim.x + threadIdx.x;
    if (i < n) { g_cnt[i] = 0; g_degout[i] = 0; }
    if (i == 0) g_ovf_n = 0;
}

// One pass over edges: out-degree histogram + dst-binning.
__global__ void k_bin(const int* __restrict__ src, const int* __restrict__ dst, int e) {
    int i = blockIdx.x * blockDim.x + threadIdx.x;
    if (i < e) {
        int s = src[i];
        int d = dst[i];
        atomicAdd(&g_degout[s], 1);
        int pos = atomicAdd(&g_cnt[d], 1);
        if (pos < CAP) {
            g_ebuf[d * CAP + pos] = s;
        } else {
            int k = atomicAdd(&g_ovf_n, 1);
            if (k < MAX_OVF) g_ovf[k] = make_int2(d, s);
        }
    }
}

__global__ void k_norm(int n) {
    int i = blockIdx.x * blockDim.x + threadIdx.x;
    if (i < n) g_srcnorm[i] = rsqrtf(fmaxf((float)g_degout[i], 1.f));
}

// Fused gather-SpMM + epilogue. One warp per destination node.
// Lane l accumulates feature columns {2l, 2l+1}.
__global__ void k_gather(const float* __restrict__ feat,
                         const float* __restrict__ hw,
                         const float* __restrict__ hb,
                         const int* __restrict__ niter_p,
                         float* __restrict__ out, int n) {
    int warp = (blockIdx.x * blockDim.x + threadIdx.x) >> 5;
    int lane = threadIdx.x & 31;
    if (warp >= n) return;
    int node = warp;

    int deg = g_cnt[node];                  // true in-degree
    int degb = min(deg, CAP);
    float dn = rsqrtf(fmaxf((float)deg, 1.f));

    const float2* F2 = (const float2*)feat;
    float2 acc = make_float2(0.f, 0.f);

    const int* bin = g_ebuf + node * CAP;
    for (int base = 0; base < degb; base += 32) {
        int m = min(32, degb - base);
        int   s_l  = (base + lane < degb) ? bin[base + lane] : 0;
        float sn_l = (base + lane < degb) ? g_srcnorm[s_l] : 0.f;
        #pragma unroll 4
        for (int k = 0; k < m; k++) {
            int   s  = __shfl_sync(0xffffffffu, s_l, k);
            float sn = __shfl_sync(0xffffffffu, sn_l, k);
            float2 v = F2[(size_t)s * 32 + lane];
            acc.x += sn * v.x;
            acc.y += sn * v.y;
        }
    }

    // Overflow edges (empty in practice; correct if not)
    if (deg > CAP) {
        int novf = min(g_ovf_n, MAX_OVF);
        for (int i = 0; i < novf; i++) {
            int2 pr = g_ovf[i];
            if (pr.x == node) {
                int s = pr.y;
                float sn = g_srcnorm[s];
                float2 v = F2[(size_t)s * 32 + lane];
                acc.x += sn * v.x;
                acc.y += sn * v.y;
            }
        }
    }

    // prop = acc * dn; halting head
    float p0 = acc.x * dn;
    float p1 = acc.y * dn;
    float2 w = ((const float2*)hw)[lane];
    float dot = w.x * p0 + w.y * p1;
    #pragma unroll
    for (int o = 16; o > 0; o >>= 1)
        dot += __shfl_xor_sync(0xffffffffu, dot, o);
    float z = dot + hb[0];
    float h = 1.f / (1.f + expf(-z));

    int niter = niter_p ? *niter_p : 10;
    float niter_f = (float)niter;

    // Exact emulation of the halting recurrence (prop/h loop-invariant, so
    // only iteration 0's p blends in `feature`; every later active iteration
    // contributes exactly `prop`). Verified bit-compatible in R1.
    float steps = 1.f, sum_h = 0.f;
    bool cont = true;
    float pfirst = 1.f;
    int U = 0;
    for (int t = 0; t < niter; ++t) {
        bool prob = (sum_h + h < 0.99f) && cont;
        if (cont) U++;
        float probf = prob ? 1.f : 0.f;
        steps += probf;
        sum_h += probf * h;
        bool condition = prob && (steps < niter_f);
        float p = condition ? sum_h : 1.f - sum_h;
        if (t == 0) pfirst = p;
        cont = cont && prob;
    }

    float cprop = pfirst + (float)(U - 1);
    float cfeat = 1.f - pfirst;

    float2 f = F2[(size_t)node * 32 + lane];
    float inv_steps = 1.f / steps;
    float2 r;
    r.x = (p0 * cprop + f.x * cfeat) * inv_steps;
    r.y = (p1 * cprop + f.y * cfeat) * inv_steps;
    ((float2*)out)[(size_t)node * 32 + lane] = r;
    if (lane == 0) {
        out[(size_t)n * H + node] = steps;            // steps
        out[(size_t)n * H + n + node] = 1.f - sum_h;  // remainder
    }
}

extern "C" void kernel_launch(void* const* d_in, const int* in_sizes, int n_in,
                              void* d_out, int out_size) {
    const float* feat = (const float*)d_in[0];
    const int*   src  = (const int*)d_in[1];
    const int*   dst  = (const int*)d_in[2];
    const float* hw   = (const float*)d_in[3];
    const float* hb   = (const float*)d_in[4];
    const int*   nit  = (n_in >= 6) ? (const int*)d_in[5] : nullptr;

    int n = in_sizes[0] / H;
    int e = in_sizes[1];
    float* out = (float*)d_out;

    k_zero<<<(n + 255) / 256, 256>>>(n);
    k_bin<<<(e + 255) / 256, 256>>>(src, dst, e);
    k_norm<<<(n + 255) / 256, 256>>>(n);
    {
        long long threads = (long long)n * 32;
        int blocks = (int)((threads + 255) / 256);
        k_gather<<<blocks, 256>>>(feat, hw, hb, nit, out, n);
    }
}

// round 3
// speedup vs baseline: 1.6765x; 1.1205x over previous
#include <cuda_runtime.h>
#include <math.h>

#define H 64
#define MAX_N 65536
#define CAP 64
#define MAX_OVF 65536

// Static scratch (no allocation in kernel_launch)
__device__ int   g_ebuf[MAX_N * CAP];   // dst-binned src indices
__device__ int   g_cnt[MAX_N];          // in-degree / bin cursor
__device__ int   g_degout[MAX_N];       // out-degree
__device__ int2  g_ovf[MAX_OVF];        // overflow (dst, src) pairs
__device__ int   g_ovf_n;

__global__ void k_zero(int n) {
    int i = blockIdx.x * blockDim.x + threadIdx.x;
    if (i < n) { g_cnt[i] = 0; g_degout[i] = 0; }
    if (i == 0) g_ovf_n = 0;
}

// One pass over edges: out-degree histogram + dst-binning.
__global__ void k_bin(const int* __restrict__ src, const int* __restrict__ dst, int e) {
    int i = blockIdx.x * blockDim.x + threadIdx.x;
    if (i < e) {
        int s = src[i];
        int d = dst[i];
        atomicAdd(&g_degout[s], 1);
        int pos = atomicAdd(&g_cnt[d], 1);
        if (pos < CAP) {
            g_ebuf[d * CAP + pos] = s;
        } else {
            int k = atomicAdd(&g_ovf_n, 1);
            if (k < MAX_OVF) g_ovf[k] = make_int2(d, s);
        }
    }
}

// Fused gather-SpMM + epilogue. TWO nodes per warp: each half-warp
// (16 lanes x float4) owns one destination node.
__global__ void k_gather(const float* __restrict__ feat,
                         const float* __restrict__ hw,
                         const float* __restrict__ hb,
                         const int* __restrict__ niter_p,
                         float* __restrict__ out, int n) {
    int gwarp = (blockIdx.x * blockDim.x + threadIdx.x) >> 5;
    int lane  = threadIdx.x & 31;
    int half  = lane >> 4;
    int hl    = lane & 15;
    int node  = gwarp * 2 + half;
    if (node >= n) return;
    unsigned hmask = 0xFFFFu << (half * 16);

    int deg  = g_cnt[node];            // true in-degree
    int degb = min(deg, CAP);
    float dn = rsqrtf(fmaxf((float)deg, 1.f));

    const float4* F4 = (const float4*)feat;
    float4 acc = make_float4(0.f, 0.f, 0.f, 0.f);

    const int* bin = g_ebuf + node * CAP;
    for (int base = 0; base < degb; base += 16) {
        int m = min(16, degb - base);
        int idx = base + hl;
        bool valid = idx < degb;
        int   s_l  = valid ? bin[idx] : 0;
        float sn_l = valid ? rsqrtf(fmaxf((float)g_degout[s_l], 1.f)) : 0.f;
        #pragma unroll 4
        for (int k = 0; k < m; k++) {
            int   s  = __shfl_sync(hmask, s_l, k, 16);
            float sn = __shfl_sync(hmask, sn_l, k, 16);
            float4 v = F4[(size_t)s * 16 + hl];
            acc.x += sn * v.x;
            acc.y += sn * v.y;
            acc.z += sn * v.z;
            acc.w += sn * v.w;
        }
    }

    // Overflow edges (empty in practice; correct if not)
    if (deg > CAP) {
        int novf = min(g_ovf_n, MAX_OVF);
        for (int i = 0; i < novf; i++) {
            int2 pr = g_ovf[i];
            if (pr.x == node) {
                int s = pr.y;
                float sn = rsqrtf(fmaxf((float)g_degout[s], 1.f));
                float4 v = F4[(size_t)s * 16 + hl];
                acc.x += sn * v.x;
                acc.y += sn * v.y;
                acc.z += sn * v.z;
                acc.w += sn * v.w;
            }
        }
    }

    // prop = acc * dn; halting head
    float4 p;
    p.x = acc.x * dn; p.y = acc.y * dn; p.z = acc.z * dn; p.w = acc.w * dn;
    float4 w = ((const float4*)hw)[hl];
    float dot = w.x * p.x + w.y * p.y + w.z * p.z + w.w * p.w;
    #pragma unroll
    for (int o = 8; o > 0; o >>= 1)
        dot += __shfl_xor_sync(hmask, dot, o, 16);
    float z = dot + hb[0];
    float h = 1.f / (1.f + expf(-z));

    int niter = niter_p ? *niter_p : 10;
    float niter_f = (float)niter;

    // Exact emulation of the halting recurrence (prop/h loop-invariant, so
    // only iteration 0's p blends in `feature`; every later active iteration
    // contributes exactly `prop`). Verified bit-compatible in R1/R2.
    float steps = 1.f, sum_h = 0.f;
    bool cont = true;
    float pfirst = 1.f;
    int U = 0;
    for (int t = 0; t < niter; ++t) {
        bool prob = (sum_h + h < 0.99f) && cont;
        if (cont) U++;
        float probf = prob ? 1.f : 0.f;
        steps += probf;
        sum_h += probf * h;
        bool condition = prob && (steps < niter_f);
        float pp = condition ? sum_h : 1.f - sum_h;
        if (t == 0) pfirst = pp;
        cont = cont && prob;
    }

    float cprop = pfirst + (float)(U - 1);
    float cfeat = 1.f - pfirst;

    float4 f = F4[(size_t)node * 16 + hl];
    float inv_steps = 1.f / steps;
    float4 r;
    r.x = (p.x * cprop + f.x * cfeat) * inv_steps;
    r.y = (p.y * cprop + f.y * cfeat) * inv_steps;
    r.z = (p.z * cprop + f.z * cfeat) * inv_steps;
    r.w = (p.w * cprop + f.w * cfeat) * inv_steps;
    ((float4*)out)[(size_t)node * 16 + hl] = r;
    if (hl == 0) {
        out[(size_t)n * H + node] = steps;            // steps
        out[(size_t)n * H + n + node] = 1.f - sum_h;  // remainder
    }
}

extern "C" void kernel_launch(void* const* d_in, const int* in_sizes, int n_in,
                              void* d_out, int out_size) {
    const float* feat = (const float*)d_in[0];
    const int*   src  = (const int*)d_in[1];
    const int*   dst  = (const int*)d_in[2];
    const float* hw   = (const float*)d_in[3];
    const float* hb   = (const float*)d_in[4];
    const int*   nit  = (n_in >= 6) ? (const int*)d_in[5] : nullptr;

    int n = in_sizes[0] / H;
    int e = in_sizes[1];
    float* out = (float*)d_out;

    k_zero<<<(n + 255) / 256, 256>>>(n);
    k_bin<<<(e + 255) / 256, 256>>>(src, dst, e);
    {
        long long threads = (long long)((n + 1) / 2) * 32;
        int blocks = (int)((threads + 255) / 256);
        k_gather<<<blocks, 256>>>(feat, hw, hb, nit, out, n);
    }
}